// round 3
// baseline (speedup 1.0000x reference)
#include <cuda_runtime.h>
#include <math.h>

#define LL   32768
#define CHN  128
#define NCHK 256
#define CHP  131
#define PAD  132

// ---------------- static device scratch ----------------
__device__ float gXf [2*48*LL];
__device__ float gYf [2*48*LL];
__device__ float gVol[2*48*LL];
__device__ float gY0 [4*48*LL];
__device__ float gSdt[4*48*LL];
__device__ float gZs [4*48*LL];
__device__ float gCm [4*8*LL];
__device__ float gHend[4*NCHK*384];
__device__ float gSsum[4*NCHK*48];
__device__ float gH0c [4*NCHK*384];

// ---------------- permute in: token order -> scan order ----------------
__global__ void k_perm_in(const float* __restrict__ xext, int useVol, int it)
{
    __shared__ float tile[32][33];
    int bc = blockIdx.y, f = blockIdx.x;
    int tx = threadIdx.x, ty = threadIdx.y;
    const float* s = (useVol ? gVol : xext) + (size_t)bc * LL;
    float* d = gXf + (size_t)bc * LL;
    if (it == 0) { int o = f*1024 + ty*32 + tx; d[o] = s[o]; return; }
    if (it == 1) {
        tile[ty][tx] = s[ty*1024 + f*32 + tx];        // (d=ty,h=f,w=tx)
        __syncthreads();
        d[f*1024 + ty*32 + tx] = tile[tx][ty];        // l=(h=f,w=ty,d=tx)
    } else {
        tile[ty][tx] = s[f*1024 + ty*32 + tx];        // (d=f,h=ty,w=tx)
        __syncthreads();
        d[ty*1024 + f*32 + tx] = tile[tx][ty];        // l=(w=ty,d=f,h=tx)
    }
}

// ---------------- permute out: scan order -> token order ----------------
__global__ void k_perm_out(float* extd, const float* __restrict__ xext, int toExt, int it)
{
    __shared__ float tile[32][33];
    int bc = blockIdx.y, f = blockIdx.x;
    int tx = threadIdx.x, ty = threadIdx.y;
    const float* s = gYf + (size_t)bc * LL;
    float* d = (toExt ? extd : gVol) + (size_t)bc * LL;
    float v; int o;
    if (it == 0) { o = f*1024 + ty*32 + tx; v = s[o]; }
    else if (it == 1) {
        tile[ty][tx] = s[f*1024 + ty*32 + tx];        // l=(h=f,w=ty,d=tx)
        __syncthreads();
        v = tile[tx][ty]; o = ty*1024 + f*32 + tx;    // tok=(d=ty,h=f,w=tx)
    } else {
        tile[ty][tx] = s[ty*1024 + f*32 + tx];        // l=(w=ty,d=f,h=tx)
        __syncthreads();
        v = tile[tx][ty]; o = f*1024 + ty*32 + tx;    // tok=(d=f,h=ty,w=tx)
    }
    d[o] = toExt ? (v + xext[(size_t)bc * LL + o]) : v;
}

// ---------------- K1: features + within-chunk scan ----------------
__global__ __launch_bounds__(384) void k_features(
    const float* __restrict__ ln_g, const float* __restrict__ ln_b,
    const float* __restrict__ in_w, const float* __restrict__ conv_w,
    const float* __restrict__ conv_b, const float* __restrict__ xproj_w,
    const float* __restrict__ dt_w, const float* __restrict__ dt_b,
    const float* __restrict__ A_log, const float* __restrict__ Dpar, int iter)
{
    int ck = blockIdx.x, e = blockIdx.y, b = blockIdx.z;
    int p = 2*iter + e, be = b*2 + e, l0 = ck*CHN, tid = threadIdx.x;

    extern __shared__ float sm[];
    float* s_x    = sm;                 // [48][PAD]
    float* s_xz   = s_x    + 48*PAD;    // [48][PAD]
    float* s_xc   = s_xz   + 48*PAD;    // [48][PAD]
    float* s_xdbl = s_xc   + 48*PAD;    // [18][PAD]
    float* s_wi   = s_xdbl + 18*PAD;    // [24][96]
    float* s_cw   = s_wi   + 24*96;     // [48][4]
    float* s_cb   = s_cw   + 192;
    float* s_xw   = s_cb   + 48;        // [18][48]
    float* s_dtw  = s_xw   + 864;       // [48][2]
    float* s_dtb  = s_dtw  + 96;
    float* s_g    = s_dtb  + 48;
    float* s_bb   = s_g    + 48;
    float* s_Dp   = s_bb   + 48;
    float* s_dt   = s_x;                // alias (x dead after in_proj)
    float* s_y0   = s_xz;               // alias (xz dead after conv)

    for (int i = tid; i < 96*24; i += 384) {
        int eo = i/24, dd = i%24;
        s_wi[dd*96 + eo] = in_w[p*96*24 + i];
    }
    for (int i = tid; i < 192; i += 384) s_cw[i] = conv_w[p*192 + i];
    for (int i = tid; i < 864; i += 384) s_xw[i] = xproj_w[p*864 + i];
    for (int i = tid; i < 96;  i += 384) s_dtw[i] = dt_w[p*96 + i];
    if (tid < 48) {
        s_cb[tid]  = conv_b[p*48 + tid];  s_dtb[tid] = dt_b[p*48 + tid];
        s_g[tid]   = ln_g[iter*48 + tid]; s_bb[tid]  = ln_b[iter*48 + tid];
        s_Dp[tid]  = Dpar[p*48 + tid];
    }
    const float* xfb = gXf + (size_t)b*48*LL;
    for (int i = tid; i < 48*PAD; i += 384) {
        int c = i/PAD, j = i%PAD;
        int l = l0 - 3 + j;
        float v = 0.f;
        if (j < CHP && l >= 0) {
            int t = (e == 0) ? l : (LL - 1 - l);
            v = xfb[(size_t)c*LL + t];
        }
        s_x[c*PAD + j] = v;
    }
    __syncthreads();

    // layernorm per token
    for (int j = tid; j < CHP; j += 384) {
        float mu = 0.f;
        #pragma unroll
        for (int c = 0; c < 48; c++) mu += s_x[c*PAD + j];
        mu *= (1.f/48.f);
        float var = 0.f;
        #pragma unroll
        for (int c = 0; c < 48; c++) { float dv = s_x[c*PAD + j] - mu; var += dv*dv; }
        float rs = rsqrtf(var*(1.f/48.f) + 1e-5f);
        #pragma unroll
        for (int c = 0; c < 48; c++)
            s_x[c*PAD + j] = (s_x[c*PAD + j] - mu)*rs*s_g[c] + s_bb[c];
    }
    __syncthreads();

    // in_proj (u = channels e*24..e*24+23)
    int c0 = e*24;
    for (int itx = tid; itx < 24*33; itx += 384) {
        int eg = itx/33, jg = itx%33;
        int e4 = eg*4, j4 = jg*4;
        float acc[4][4] = {};
        #pragma unroll
        for (int dd = 0; dd < 24; dd++) {
            float4 xv = *(const float4*)&s_x[(c0+dd)*PAD + j4];
            float4 wv = *(const float4*)&s_wi[dd*96 + e4];
            acc[0][0]+=wv.x*xv.x; acc[0][1]+=wv.x*xv.y; acc[0][2]+=wv.x*xv.z; acc[0][3]+=wv.x*xv.w;
            acc[1][0]+=wv.y*xv.x; acc[1][1]+=wv.y*xv.y; acc[1][2]+=wv.y*xv.z; acc[1][3]+=wv.y*xv.w;
            acc[2][0]+=wv.z*xv.x; acc[2][1]+=wv.z*xv.y; acc[2][2]+=wv.z*xv.z; acc[2][3]+=wv.z*xv.w;
            acc[3][0]+=wv.w*xv.x; acc[3][1]+=wv.w*xv.y; acc[3][2]+=wv.w*xv.z; acc[3][3]+=wv.w*xv.w;
        }
        int gl = l0 - 3 + j4;
        #pragma unroll
        for (int ee = 0; ee < 4; ee++) {
            int eo = e4 + ee;
            #pragma unroll
            for (int jj = 0; jj < 4; jj++) {
                int j = j4 + jj;
                if (j >= CHP) continue;
                float v = (gl + jj < 0) ? 0.f : acc[ee][jj];
                if (eo < 48) s_xz[eo*PAD + j] = v;
                else if (j >= 3) {
                    float zs = v / (1.f + __expf(-v));
                    gZs[((size_t)(be*48) + (eo-48))*LL + (size_t)(l0 + j - 3)] = zs;
                }
            }
        }
    }
    __syncthreads();

    // causal conv(4) + silu
    for (int itx = tid; itx < 48*CHN; itx += 384) {
        int d = itx/CHN, t = itx%CHN;
        float v = s_cb[d]
                + s_cw[d*4+0]*s_xz[d*PAD + t]
                + s_cw[d*4+1]*s_xz[d*PAD + t+1]
                + s_cw[d*4+2]*s_xz[d*PAD + t+2]
                + s_cw[d*4+3]*s_xz[d*PAD + t+3];
        s_xc[d*PAD + t] = v / (1.f + __expf(-v));
    }
    __syncthreads();

    // x_proj
    for (int itx = tid; itx < 18*32; itx += 384) {
        int e2 = itx/32, t4 = (itx%32)*4;
        float a0=0,a1=0,a2=0,a3=0;
        #pragma unroll
        for (int d = 0; d < 48; d++) {
            float w = s_xw[e2*48 + d];
            float4 xv = *(const float4*)&s_xc[d*PAD + t4];
            a0 += w*xv.x; a1 += w*xv.y; a2 += w*xv.z; a3 += w*xv.w;
        }
        float4 st = {a0,a1,a2,a3};
        *(float4*)&s_xdbl[e2*PAD + t4] = st;
    }
    __syncthreads();

    // dt = softplus(dt_in @ dtw^T + dtb)   (writes alias s_dt = s_x)
    for (int itx = tid; itx < 48*CHN; itx += 384) {
        int d = itx/CHN, t = itx%CHN;
        float v = s_dtb[d] + s_dtw[d*2+0]*s_xdbl[0*PAD+t] + s_dtw[d*2+1]*s_xdbl[1*PAD+t];
        s_dt[d*PAD + t] = (v > 20.f) ? v : log1pf(__expf(v));
    }
    __syncthreads();

    // within-chunk scan, thread = (d,s)
    {
        int d = tid >> 3, s = tid & 7;
        float A_ds = -expf(A_log[(p*48 + d)*8 + s]);
        float h = 0.f, run = 0.f;
        for (int t = 0; t < CHN; t++) {
            float dtv = s_dt[d*PAD + t];
            float Bv  = s_xdbl[(2+s)*PAD + t];
            float Cv  = s_xdbl[(10+s)*PAD + t];
            float xcv = s_xc[d*PAD + t];
            h = __expf(dtv*A_ds)*h + dtv*Bv*xcv;
            float yc = h*Cv;
            yc += __shfl_xor_sync(0xFFFFFFFFu, yc, 4);
            yc += __shfl_xor_sync(0xFFFFFFFFu, yc, 2);
            yc += __shfl_xor_sync(0xFFFFFFFFu, yc, 1);
            run += dtv;
            __syncwarp();
            if (s == 0) { s_y0[d*PAD + t] = yc; s_dt[d*PAD + t] = run; }
            __syncwarp();
        }
        gHend[(size_t)(be*NCHK + ck)*384 + d*8 + s] = h;
        if (s == 0) gSsum[(size_t)(be*NCHK + ck)*48 + d] = run;
    }
    __syncthreads();

    // write chunk outputs (coalesced)
    size_t baseF = (size_t)(be*48)*LL + l0;
    for (int itx = tid; itx < 48*CHN; itx += 384) {
        int d = itx>>7, t = itx&127;
        gY0 [baseF + (size_t)d*LL + t] = s_y0[d*PAD+t] + s_xc[d*PAD+t]*s_Dp[d];
        gSdt[baseF + (size_t)d*LL + t] = s_dt[d*PAD+t];
    }
    for (int itx = tid; itx < 8*CHN; itx += 384) {
        int ss = itx>>7, t = itx&127;
        gCm[(size_t)(be*8 + ss)*LL + l0 + t] = s_xdbl[(10+ss)*PAD + t];
    }
}

// ---------------- K2: serial carry combine ----------------
__global__ __launch_bounds__(384) void k_combine(const float* __restrict__ A_log, int iter)
{
    int be = blockIdx.x, e = be & 1, p = 2*iter + e;
    int tid = threadIdx.x, d = tid >> 3, s = tid & 7;
    float A_ds = -expf(A_log[(p*48 + d)*8 + s]);
    float hrun = 0.f;
    const int G = 16;
    float hv[G], Sv[G];
    for (int g0 = 0; g0 < NCHK; g0 += G) {
        #pragma unroll
        for (int k = 0; k < G; k++) {
            int ck = g0 + k;
            hv[k] = gHend[(size_t)(be*NCHK + ck)*384 + tid];
            Sv[k] = gSsum[(size_t)(be*NCHK + ck)*48 + d];
        }
        #pragma unroll
        for (int k = 0; k < G; k++) {
            int ck = g0 + k;
            gH0c[(size_t)(be*NCHK + ck)*384 + tid] = hrun;
            hrun = __expf(Sv[k]*A_ds)*hrun + hv[k];
        }
    }
}

// ---------------- K3: correction + gate + out_proj + residual ----------------
__global__ __launch_bounds__(384) void k_output(
    const float* __restrict__ A_log, const float* __restrict__ out_w, int iter)
{
    int ck = blockIdx.x, e = blockIdx.y, b = blockIdx.z;
    int p = 2*iter + e, be = b*2 + e, l0 = ck*CHN, tid = threadIdx.x;

    extern __shared__ float sm[];
    float* s_y  = sm;            // [48][128]
    float* s_Cm = s_y  + 48*128; // [8][128]
    float* s_h0 = s_Cm + 8*128;  // [384]
    float* s_A  = s_h0 + 384;    // [384]
    float* s_ow = s_A  + 384;    // [24][48]

    if (tid < 384) {
        s_h0[tid] = gH0c[(size_t)(be*NCHK + ck)*384 + tid];
        s_A[tid]  = -expf(A_log[p*384 + tid]);
    }
    for (int i = tid; i < 24*48; i += 384) s_ow[i] = out_w[p*1152 + i];
    for (int i = tid; i < 8*128; i += 384) {
        int ss = i>>7, t = i&127;
        s_Cm[i] = gCm[(size_t)(be*8 + ss)*LL + l0 + t];
    }
    __syncthreads();

    size_t baseF = (size_t)(be*48)*LL + l0;
    for (int itx = tid; itx < 48*128; itx += 384) {
        int d = itx>>7, t = itx&127;
        float sd  = gSdt[baseF + (size_t)d*LL + t];
        float acc = gY0 [baseF + (size_t)d*LL + t];
        #pragma unroll
        for (int s = 0; s < 8; s++)
            acc += s_Cm[s*128 + t] * __expf(sd * s_A[d*8 + s]) * s_h0[d*8 + s];
        acc *= gZs[baseF + (size_t)d*LL + t];
        s_y[d*128 + t] = acc;
    }
    __syncthreads();

    for (int itx = tid; itx < 24*128; itx += 384) {
        int m = itx>>7, t = itx&127;
        float a = 0.f;
        #pragma unroll
        for (int d = 0; d < 48; d++) a += s_ow[m*48 + d]*s_y[d*128 + t];
        int c = e*24 + m;
        int tp = (e == 0) ? (l0 + t) : (LL - 1 - (l0 + t));
        size_t o = (size_t)(b*48 + c)*LL + tp;
        gYf[o] = a + gXf[o];
    }
}

#define SMEM_K1 ((3*48*PAD + 18*PAD + 24*96 + 192 + 48 + 864 + 96 + 48 + 48 + 48 + 48) * 4)
#define SMEM_K3 ((48*128 + 8*128 + 384 + 384 + 24*48) * 4)

extern "C" void kernel_launch(void* const* d_in, const int* in_sizes, int n_in,
                              void* d_out, int out_size)
{
    const float* x       = (const float*)d_in[0];
    const float* ln_g    = (const float*)d_in[1];
    const float* ln_b    = (const float*)d_in[2];
    const float* in_w    = (const float*)d_in[3];
    const float* conv_w  = (const float*)d_in[4];
    const float* conv_b  = (const float*)d_in[5];
    const float* xproj_w = (const float*)d_in[6];
    const float* dt_w    = (const float*)d_in[7];
    const float* dt_b    = (const float*)d_in[8];
    const float* A_log   = (const float*)d_in[9];
    const float* Dp      = (const float*)d_in[10];
    const float* out_w   = (const float*)d_in[11];
    float* out = (float*)d_out;

    cudaFuncSetAttribute(k_features, cudaFuncAttributeMaxDynamicSharedMemorySize, SMEM_K1);

    dim3 pg(32, 96), pb(32, 32);
    for (int it = 0; it < 3; ++it) {
        k_perm_in<<<pg, pb>>>(x, it == 0 ? 0 : 1, it);
        k_features<<<dim3(NCHK,2,2), 384, SMEM_K1>>>(ln_g, ln_b, in_w, conv_w, conv_b,
                                                     xproj_w, dt_w, dt_b, A_log, Dp, it);
        k_combine<<<4, 384>>>(A_log, it);
        k_output<<<dim3(NCHK,2,2), 384, SMEM_K3>>>(A_log, out_w, it);
        k_perm_out<<<pg, pb>>>(out, x, it == 2 ? 1 : 0, it);
    }
}

// round 4
// speedup vs baseline: 1.1874x; 1.1874x over previous
#include <cuda_runtime.h>
#include <math.h>

#define LL   32768
#define CHN  128
#define NCHK 256
#define CHP  131
#define PAD  132

// ---------------- static device scratch ----------------
__device__ float gXf [2*48*LL];
__device__ float gYf [2*48*LL];
__device__ float gY0 [4*48*LL];
__device__ float gSdt[4*48*LL];
__device__ float gZs [4*48*LL];
__device__ float gCm [4*8*LL];
__device__ float gHend[4*NCHK*384];
__device__ float gSsum[4*NCHK*48];
__device__ float gH0c [4*NCHK*384];

// ---------------- fused rotation: gYf (scan order it) -> gXf (scan order it+1) ----------------
// out[b*1024 + c*32 + a] = in[a*1024 + b*32 + c]
__global__ void k_rot()
{
    __shared__ float tile[32][33];
    int bc = blockIdx.y, f = blockIdx.x;
    int tx = threadIdx.x, ty = threadIdx.y;
    const float* s = gYf + (size_t)bc * LL;
    float* d = gXf + (size_t)bc * LL;
    tile[ty][tx] = s[ty*1024 + f*32 + tx];     // a=ty, b=f, c=tx
    __syncthreads();
    d[f*1024 + ty*32 + tx] = tile[tx][ty];     // c=ty, a=tx
}

// ---------------- final: gYf (it=2 scan order l=(w,d,h)) -> token order + x ----------------
__global__ void k_final(float* extd, const float* __restrict__ xext)
{
    __shared__ float tile[32][33];
    int bc = blockIdx.y, f = blockIdx.x;
    int tx = threadIdx.x, ty = threadIdx.y;
    const float* s = gYf + (size_t)bc * LL;
    tile[ty][tx] = s[ty*1024 + f*32 + tx];     // w=ty, d=f, h=tx
    __syncthreads();
    int o = f*1024 + ty*32 + tx;               // tok (d=f,h=ty,w=tx) -> val at (w=tx,d=f,h=ty)
    extd[(size_t)bc*LL + o] = tile[tx][ty] + xext[(size_t)bc*LL + o];
}

// ---------------- K1: features + hierarchical within-chunk scan ----------------
__global__ __launch_bounds__(384, 2) void k_features(
    const float* __restrict__ ln_g, const float* __restrict__ ln_b,
    const float* __restrict__ in_w, const float* __restrict__ conv_w,
    const float* __restrict__ conv_b, const float* __restrict__ xproj_w,
    const float* __restrict__ dt_w, const float* __restrict__ dt_b,
    const float* __restrict__ A_log, const float* __restrict__ Dpar,
    const float* __restrict__ xext, int useX, int iter)
{
    int ck = blockIdx.x, e = blockIdx.y, b = blockIdx.z;
    int p = 2*iter + e, be = b*2 + e, l0 = ck*CHN, tid = threadIdx.x;

    extern __shared__ float sm[];
    float* s_x    = sm;                 // [48][PAD]
    float* s_xz   = s_x    + 48*PAD;    // [48][PAD]
    float* s_xc   = s_xz   + 48*PAD;    // [48][PAD]
    float* s_dtin = s_xc   + 48*PAD;    // [2][PAD]
    float* s_bt   = s_dtin + 2*PAD;     // [128 tok][20] swizzled: B0..7,C0..7
    float* s_wi   = s_bt   + 2592;      // [24][96]
    float* s_cw   = s_wi   + 24*96;     // [48][4]
    float* s_cb   = s_cw   + 192;
    float* s_xw   = s_cb   + 48;        // [18][48]
    float* s_dtw  = s_xw   + 864;       // [48][2]
    float* s_dtb  = s_dtw  + 96;
    float* s_g    = s_dtb  + 48;
    float* s_bb   = s_g    + 48;
    float* s_Dp   = s_bb   + 48;
    float* s_dt   = s_x;                // alias (x dead after in_proj)
    float* s_y0   = s_xz;               // alias (xz dead after conv)

    for (int i = tid; i < 96*24; i += 384) {
        int eo = i/24, dd = i%24;
        s_wi[dd*96 + eo] = in_w[p*96*24 + i];
    }
    for (int i = tid; i < 192; i += 384) s_cw[i] = conv_w[p*192 + i];
    for (int i = tid; i < 864; i += 384) s_xw[i] = xproj_w[p*864 + i];
    for (int i = tid; i < 96;  i += 384) s_dtw[i] = dt_w[p*96 + i];
    if (tid < 48) {
        s_cb[tid]  = conv_b[p*48 + tid];  s_dtb[tid] = dt_b[p*48 + tid];
        s_g[tid]   = ln_g[iter*48 + tid]; s_bb[tid]  = ln_b[iter*48 + tid];
        s_Dp[tid]  = Dpar[p*48 + tid];
    }
    const float* xfb = (useX ? xext : (const float*)gXf) + (size_t)b*48*LL;
    for (int i = tid; i < 48*PAD; i += 384) {
        int c = i/PAD, j = i%PAD;
        int l = l0 - 3 + j;
        float v = 0.f;
        if (j < CHP && l >= 0) {
            int t = (e == 0) ? l : (LL - 1 - l);
            v = xfb[(size_t)c*LL + t];
        }
        s_x[c*PAD + j] = v;
    }
    __syncthreads();

    // layernorm per token
    for (int j = tid; j < CHP; j += 384) {
        float mu = 0.f;
        #pragma unroll
        for (int c = 0; c < 48; c++) mu += s_x[c*PAD + j];
        mu *= (1.f/48.f);
        float var = 0.f;
        #pragma unroll
        for (int c = 0; c < 48; c++) { float dv = s_x[c*PAD + j] - mu; var += dv*dv; }
        float rs = rsqrtf(var*(1.f/48.f) + 1e-5f);
        #pragma unroll
        for (int c = 0; c < 48; c++)
            s_x[c*PAD + j] = (s_x[c*PAD + j] - mu)*rs*s_g[c] + s_bb[c];
    }
    __syncthreads();

    // in_proj
    int c0 = e*24;
    for (int itx = tid; itx < 24*33; itx += 384) {
        int eg = itx/33, jg = itx%33;
        int e4 = eg*4, j4 = jg*4;
        float acc[4][4] = {};
        #pragma unroll
        for (int dd = 0; dd < 24; dd++) {
            float4 xv = *(const float4*)&s_x[(c0+dd)*PAD + j4];
            float4 wv = *(const float4*)&s_wi[dd*96 + e4];
            acc[0][0]+=wv.x*xv.x; acc[0][1]+=wv.x*xv.y; acc[0][2]+=wv.x*xv.z; acc[0][3]+=wv.x*xv.w;
            acc[1][0]+=wv.y*xv.x; acc[1][1]+=wv.y*xv.y; acc[1][2]+=wv.y*xv.z; acc[1][3]+=wv.y*xv.w;
            acc[2][0]+=wv.z*xv.x; acc[2][1]+=wv.z*xv.y; acc[2][2]+=wv.z*xv.z; acc[2][3]+=wv.z*xv.w;
            acc[3][0]+=wv.w*xv.x; acc[3][1]+=wv.w*xv.y; acc[3][2]+=wv.w*xv.z; acc[3][3]+=wv.w*xv.w;
        }
        int gl = l0 - 3 + j4;
        #pragma unroll
        for (int ee = 0; ee < 4; ee++) {
            int eo = e4 + ee;
            #pragma unroll
            for (int jj = 0; jj < 4; jj++) {
                int j = j4 + jj;
                if (j >= CHP) continue;
                float v = (gl + jj < 0) ? 0.f : acc[ee][jj];
                if (eo < 48) s_xz[eo*PAD + j] = v;
                else if (j >= 3) {
                    float zs = v / (1.f + __expf(-v));
                    gZs[((size_t)(be*48) + (eo-48))*LL + (size_t)(l0 + j - 3)] = zs;
                }
            }
        }
    }
    __syncthreads();

    // causal conv(4) + silu
    for (int itx = tid; itx < 48*CHN; itx += 384) {
        int d = itx/CHN, t = itx%CHN;
        float v = s_cb[d]
                + s_cw[d*4+0]*s_xz[d*PAD + t]
                + s_cw[d*4+1]*s_xz[d*PAD + t+1]
                + s_cw[d*4+2]*s_xz[d*PAD + t+2]
                + s_cw[d*4+3]*s_xz[d*PAD + t+3];
        s_xc[d*PAD + t] = v / (1.f + __expf(-v));
    }
    __syncthreads();

    // x_proj: e2<2 -> s_dtin rows, e2>=2 -> token-major swizzled s_bt
    for (int itx = tid; itx < 18*32; itx += 384) {
        int e2 = itx/32, t4 = (itx%32)*4;
        float a[4] = {0,0,0,0};
        #pragma unroll
        for (int d = 0; d < 48; d++) {
            float w = s_xw[e2*48 + d];
            float4 xv = *(const float4*)&s_xc[d*PAD + t4];
            a[0] += w*xv.x; a[1] += w*xv.y; a[2] += w*xv.z; a[3] += w*xv.w;
        }
        if (e2 < 2) {
            float4 st = {a[0],a[1],a[2],a[3]};
            *(float4*)&s_dtin[e2*PAD + t4] = st;
        } else {
            int c = e2 - 2;
            int swz = ((t4 >> 4) & 7) * 4;
            #pragma unroll
            for (int k = 0; k < 4; k++)
                s_bt[(t4+k)*20 + swz + c] = a[k];
        }
    }
    __syncthreads();

    // dt = softplus(dt_in @ dtw^T + dtb)  (alias s_dt = s_x)
    for (int itx = tid; itx < 48*CHN; itx += 384) {
        int d = itx/CHN, t = itx%CHN;
        float v = s_dtb[d] + s_dtw[d*2+0]*s_dtin[t] + s_dtw[d*2+1]*s_dtin[PAD + t];
        s_dt[d*PAD + t] = (v > 20.f) ? v : log1pf(__expf(v));
    }
    __syncthreads();

    // ---- hierarchical scan: thread = (d, sub of 16 tokens) ----
    {
        int d = tid >> 3, sub = tid & 7;
        int t0 = sub * 16;
        float Av[8];
        #pragma unroll
        for (int s = 0; s < 8; s++) Av[s] = -__expf(A_log[p*384 + d*8 + s]);
        float A0 = Av[0];
        bool fast = true;
        #pragma unroll
        for (int s = 1; s < 8; s++)
            if (fabsf(Av[s] - (float)(s+1)*A0) > 1e-4f * fabsf(Av[s])) fast = false;

        float h[8] = {0,0,0,0,0,0,0,0};
        float run = 0.f;
        // pass 1: local scan (h0=0 at sub start), store local y0 and local dt-prefix
        for (int tt = 0; tt < 16; tt++) {
            int t = t0 + tt;
            float dtv = s_dt[d*PAD + t];
            float xcv = s_xc[d*PAD + t];
            run += dtv;
            s_dt[d*PAD + t] = run;
            float dx = dtv * xcv;
            int rb = t*20 + sub*4;
            float4 b0 = *(const float4*)&s_bt[rb];
            float4 b1 = *(const float4*)&s_bt[rb+4];
            float4 cc0 = *(const float4*)&s_bt[rb+8];
            float4 cc1 = *(const float4*)&s_bt[rb+12];
            float Bv[8] = {b0.x,b0.y,b0.z,b0.w,b1.x,b1.y,b1.z,b1.w};
            float Cv[8] = {cc0.x,cc0.y,cc0.z,cc0.w,cc1.x,cc1.y,cc1.z,cc1.w};
            float y0 = 0.f;
            if (fast) {
                float q = __expf(dtv * A0), pc = q;
                #pragma unroll
                for (int s = 0; s < 8; s++) { h[s] = pc*h[s] + dx*Bv[s]; y0 += h[s]*Cv[s]; pc *= q; }
            } else {
                #pragma unroll
                for (int s = 0; s < 8; s++) { h[s] = __expf(dtv*Av[s])*h[s] + dx*Bv[s]; y0 += h[s]*Cv[s]; }
            }
            s_y0[d*PAD + t] = y0;
        }
        // Kogge-Stone inclusive scan over 8 subs (within warp, width 8)
        float S = run;
        #pragma unroll
        for (int st = 1; st < 8; st <<= 1) {
            float Sp = __shfl_up_sync(0xFFFFFFFFu, S, st, 8);
            float hp[8];
            #pragma unroll
            for (int s = 0; s < 8; s++) hp[s] = __shfl_up_sync(0xFFFFFFFFu, h[s], st, 8);
            if (sub >= st) {
                if (fast) {
                    float q = __expf(S * A0), pc = q;
                    #pragma unroll
                    for (int s = 0; s < 8; s++) { h[s] = pc*hp[s] + h[s]; pc *= q; }
                } else {
                    #pragma unroll
                    for (int s = 0; s < 8; s++) h[s] = __expf(S*Av[s])*hp[s] + h[s];
                }
                S += Sp;
            }
        }
        // exclusive (state at sub start)
        float Hex[8], Sex;
        #pragma unroll
        for (int s = 0; s < 8; s++) Hex[s] = __shfl_up_sync(0xFFFFFFFFu, h[s], 1, 8);
        Sex = __shfl_up_sync(0xFFFFFFFFu, S, 1, 8);
        if (sub == 0) {
            Sex = 0.f;
            #pragma unroll
            for (int s = 0; s < 8; s++) Hex[s] = 0.f;
        }
        if (sub == 7) {
            #pragma unroll
            for (int s = 0; s < 8; s++)
                gHend[(size_t)(be*NCHK + ck)*384 + d*8 + s] = h[s];
            gSsum[(size_t)(be*NCHK + ck)*48 + d] = S;
        }
        // pass 2: add sub-carry correction, make dt-prefix chunk-global
        for (int tt = 0; tt < 16; tt++) {
            int t = t0 + tt;
            float Sloc = s_dt[d*PAD + t];
            float y = s_y0[d*PAD + t];
            int rb = t*20 + sub*4 + 8;
            float4 cc0 = *(const float4*)&s_bt[rb];
            float4 cc1 = *(const float4*)&s_bt[rb+4];
            float Cv[8] = {cc0.x,cc0.y,cc0.z,cc0.w,cc1.x,cc1.y,cc1.z,cc1.w};
            if (fast) {
                float r = __expf(Sloc * A0), pc = r;
                #pragma unroll
                for (int s = 0; s < 8; s++) { y += Cv[s]*pc*Hex[s]; pc *= r; }
            } else {
                #pragma unroll
                for (int s = 0; s < 8; s++) y += Cv[s]*__expf(Sloc*Av[s])*Hex[s];
            }
            s_y0[d*PAD + t] = y;
            s_dt[d*PAD + t] = Sloc + Sex;
        }
    }
    __syncthreads();

    // write chunk outputs (coalesced)
    size_t baseF = (size_t)(be*48)*LL + l0;
    for (int itx = tid; itx < 48*CHN; itx += 384) {
        int d = itx>>7, t = itx&127;
        gY0 [baseF + (size_t)d*LL + t] = s_y0[d*PAD+t] + s_xc[d*PAD+t]*s_Dp[d];
        gSdt[baseF + (size_t)d*LL + t] = s_dt[d*PAD+t];
    }
    for (int itx = tid; itx < 8*CHN; itx += 384) {
        int ss = itx>>7, t = itx&127;
        gCm[(size_t)(be*8 + ss)*LL + l0 + t] = s_bt[t*20 + ((t>>4)&7)*4 + 8 + ss];
    }
}

// ---------------- K2: serial carry combine ----------------
__global__ __launch_bounds__(384) void k_combine(const float* __restrict__ A_log, int iter)
{
    int be = blockIdx.x, e = be & 1, p = 2*iter + e;
    int tid = threadIdx.x, d = tid >> 3;
    float A_ds = -expf(A_log[p*384 + tid]);
    float hrun = 0.f;
    const int G = 16;
    float hv[G], Sv[G];
    for (int g0 = 0; g0 < NCHK; g0 += G) {
        #pragma unroll
        for (int k = 0; k < G; k++) {
            int ck = g0 + k;
            hv[k] = gHend[(size_t)(be*NCHK + ck)*384 + tid];
            Sv[k] = gSsum[(size_t)(be*NCHK + ck)*48 + d];
        }
        #pragma unroll
        for (int k = 0; k < G; k++) {
            int ck = g0 + k;
            gH0c[(size_t)(be*NCHK + ck)*384 + tid] = hrun;
            hrun = __expf(Sv[k]*A_ds)*hrun + hv[k];
        }
    }
}

// ---------------- K3: correction + gate + out_proj + residual ----------------
__global__ __launch_bounds__(384, 3) void k_output(
    const float* __restrict__ A_log, const float* __restrict__ out_w,
    const float* __restrict__ xext, int useX, int iter)
{
    int ck = blockIdx.x, e = blockIdx.y, b = blockIdx.z;
    int p = 2*iter + e, be = b*2 + e, l0 = ck*CHN, tid = threadIdx.x;

    extern __shared__ float sm[];
    float* s_y    = sm;              // [48][128]
    float* s_Cm   = s_y  + 48*128;   // [8][128]
    float* s_h0   = s_Cm + 8*128;    // [384]
    float* s_A    = s_h0 + 384;      // [384]
    float* s_ow   = s_A  + 384;      // [24][48]
    float* s_fast = s_ow + 24*48;    // [48]

    s_h0[tid] = gH0c[(size_t)(be*NCHK + ck)*384 + tid];
    s_A[tid]  = -__expf(A_log[p*384 + tid]);
    for (int i = tid; i < 24*48; i += 384) s_ow[i] = out_w[p*1152 + i];
    for (int i = tid; i < 8*128; i += 384) {
        int ss = i>>7, t = i&127;
        s_Cm[i] = gCm[(size_t)(be*8 + ss)*LL + l0 + t];
    }
    if (tid < 48) {
        float a0 = -__expf(A_log[p*384 + tid*8]);
        float ok = 1.f;
        #pragma unroll
        for (int s = 1; s < 8; s++) {
            float as = -__expf(A_log[p*384 + tid*8 + s]);
            if (fabsf(as - (float)(s+1)*a0) > 1e-4f * fabsf(as)) ok = 0.f;
        }
        s_fast[tid] = ok;
    }
    __syncthreads();

    size_t baseF = (size_t)(be*48)*LL + l0;
    for (int itx = tid; itx < 48*128; itx += 384) {
        int d = itx>>7, t = itx&127;
        float sd  = gSdt[baseF + (size_t)d*LL + t];
        float acc = gY0 [baseF + (size_t)d*LL + t];
        if (s_fast[d] != 0.f) {
            float r = __expf(sd * s_A[d*8]), pc = r;
            #pragma unroll
            for (int s = 0; s < 8; s++) { acc += s_Cm[s*128 + t] * pc * s_h0[d*8 + s]; pc *= r; }
        } else {
            #pragma unroll
            for (int s = 0; s < 8; s++)
                acc += s_Cm[s*128 + t] * __expf(sd * s_A[d*8 + s]) * s_h0[d*8 + s];
        }
        acc *= gZs[baseF + (size_t)d*LL + t];
        s_y[d*128 + t] = acc;
    }
    __syncthreads();

    const float* resb = (useX ? xext : (const float*)gXf);
    for (int itx = tid; itx < 24*128; itx += 384) {
        int m = itx>>7, t = itx&127;
        float a = 0.f;
        #pragma unroll
        for (int d = 0; d < 48; d++) a += s_ow[m*48 + d]*s_y[d*128 + t];
        int c = e*24 + m;
        int tp = (e == 0) ? (l0 + t) : (LL - 1 - (l0 + t));
        size_t o = (size_t)(b*48 + c)*LL + tp;
        gYf[o] = a + resb[o];
    }
}

#define SMEM_K1 ((3*48*PAD + 2*PAD + 2592 + 24*96 + 192 + 48 + 864 + 96 + 48 + 48 + 48 + 48) * 4)
#define SMEM_K3 ((48*128 + 8*128 + 384 + 384 + 24*48 + 48) * 4)

extern "C" void kernel_launch(void* const* d_in, const int* in_sizes, int n_in,
                              void* d_out, int out_size)
{
    const float* x       = (const float*)d_in[0];
    const float* ln_g    = (const float*)d_in[1];
    const float* ln_b    = (const float*)d_in[2];
    const float* in_w    = (const float*)d_in[3];
    const float* conv_w  = (const float*)d_in[4];
    const float* conv_b  = (const float*)d_in[5];
    const float* xproj_w = (const float*)d_in[6];
    const float* dt_w    = (const float*)d_in[7];
    const float* dt_b    = (const float*)d_in[8];
    const float* A_log   = (const float*)d_in[9];
    const float* Dp      = (const float*)d_in[10];
    const float* out_w   = (const float*)d_in[11];
    float* out = (float*)d_out;

    cudaFuncSetAttribute(k_features, cudaFuncAttributeMaxDynamicSharedMemorySize, SMEM_K1);

    dim3 pg(32, 96), pb(32, 32);
    for (int it = 0; it < 3; ++it) {
        int useX = (it == 0) ? 1 : 0;
        k_features<<<dim3(NCHK,2,2), 384, SMEM_K1>>>(ln_g, ln_b, in_w, conv_w, conv_b,
                                                     xproj_w, dt_w, dt_b, A_log, Dp,
                                                     x, useX, it);
        k_combine<<<4, 384>>>(A_log, it);
        k_output<<<dim3(NCHK,2,2), 384, SMEM_K3>>>(A_log, out_w, x, useX, it);
        if (it < 2) k_rot<<<pg, pb>>>();
        else        k_final<<<pg, pb>>>(out, x);
    }
}

// round 5
// speedup vs baseline: 1.2026x; 1.0128x over previous
#include <cuda_runtime.h>
#include <math.h>

#define LL   32768
#define CHN  128
#define NCHK 256
#define CHP  131
#define PAD  132

// ---------------- static device scratch ----------------
__device__ float gXf [2*48*LL];
__device__ float gYf [2*48*LL];
__device__ float gY0 [4*48*LL];
__device__ float gSdt[4*48*LL];
__device__ float gZs [4*48*LL];
__device__ float gCm [4*8*LL];
__device__ float gHend[4*NCHK*384];
__device__ float gSsum[4*NCHK*48];
__device__ float gH0c [4*NCHK*384];

// ---------------- fused rotation: gYf (scan order it) -> gXf (scan order it+1) ----------------
__global__ void k_rot()
{
    __shared__ float tile[32][33];
    int bc = blockIdx.y, f = blockIdx.x;
    int tx = threadIdx.x, ty = threadIdx.y;
    const float* s = gYf + (size_t)bc * LL;
    float* d = gXf + (size_t)bc * LL;
    tile[ty][tx] = s[ty*1024 + f*32 + tx];
    __syncthreads();
    d[f*1024 + ty*32 + tx] = tile[tx][ty];
}

// ---------------- final: gYf (it=2 scan order) -> token order + x ----------------
__global__ void k_final(float* extd, const float* __restrict__ xext)
{
    __shared__ float tile[32][33];
    int bc = blockIdx.y, f = blockIdx.x;
    int tx = threadIdx.x, ty = threadIdx.y;
    const float* s = gYf + (size_t)bc * LL;
    tile[ty][tx] = s[ty*1024 + f*32 + tx];
    __syncthreads();
    int o = f*1024 + ty*32 + tx;
    extd[(size_t)bc*LL + o] = tile[tx][ty] + xext[(size_t)bc*LL + o];
}

// ---------------- K1: features + register-resident hierarchical scan ----------------
__global__ __launch_bounds__(384, 2) void k_features(
    const float* __restrict__ ln_g, const float* __restrict__ ln_b,
    const float* __restrict__ in_w, const float* __restrict__ conv_w,
    const float* __restrict__ conv_b, const float* __restrict__ xproj_w,
    const float* __restrict__ dt_w, const float* __restrict__ dt_b,
    const float* __restrict__ A_log, const float* __restrict__ Dpar,
    const float* __restrict__ xext, int useX, int iter)
{
    int ck = blockIdx.x, e = blockIdx.y, b = blockIdx.z;
    int p = 2*iter + e, be = b*2 + e, l0 = ck*CHN, tid = threadIdx.x;

    extern __shared__ float sm[];
    float* s_x    = sm;                 // [48][PAD]
    float* s_xz   = s_x    + 48*PAD;    // [48][PAD]
    float* s_xc   = s_xz   + 48*PAD;    // [48][PAD]
    float* s_dtin = s_xc   + 48*PAD;    // [2][PAD]
    float* s_bt   = s_dtin + 2*PAD;     // [128 tok][20] swizzled B0..7,C0..7
    float* s_wi   = s_bt   + 2592;      // [24][96]
    float* s_cw   = s_wi   + 24*96;     // [48][4]
    float* s_cb   = s_cw   + 192;
    float* s_xw   = s_cb   + 48;        // [18][48]
    float* s_dtw  = s_xw   + 864;       // [48][2]
    float* s_dtb  = s_dtw  + 96;
    float* s_g    = s_dtb  + 48;
    float* s_bb   = s_g    + 48;
    float* s_Dp   = s_bb   + 48;

    for (int i = tid; i < 96*24; i += 384) {
        int eo = i/24, dd = i%24;
        s_wi[dd*96 + eo] = in_w[p*96*24 + i];
    }
    for (int i = tid; i < 192; i += 384) s_cw[i] = conv_w[p*192 + i];
    for (int i = tid; i < 864; i += 384) s_xw[i] = xproj_w[p*864 + i];
    for (int i = tid; i < 96;  i += 384) s_dtw[i] = dt_w[p*96 + i];
    if (tid < 48) {
        s_cb[tid]  = conv_b[p*48 + tid];  s_dtb[tid] = dt_b[p*48 + tid];
        s_g[tid]   = ln_g[iter*48 + tid]; s_bb[tid]  = ln_b[iter*48 + tid];
        s_Dp[tid]  = Dpar[p*48 + tid];
    }
    const float* xfb = (useX ? xext : (const float*)gXf) + (size_t)b*48*LL;
    for (int i = tid; i < 48*PAD; i += 384) {
        int c = i/PAD, j = i%PAD;
        int l = l0 - 3 + j;
        float v = 0.f;
        if (j < CHP && l >= 0) {
            int t = (e == 0) ? l : (LL - 1 - l);
            v = xfb[(size_t)c*LL + t];
        }
        s_x[c*PAD + j] = v;
    }
    __syncthreads();

    // layernorm per token
    for (int j = tid; j < CHP; j += 384) {
        float mu = 0.f;
        #pragma unroll
        for (int c = 0; c < 48; c++) mu += s_x[c*PAD + j];
        mu *= (1.f/48.f);
        float var = 0.f;
        #pragma unroll
        for (int c = 0; c < 48; c++) { float dv = s_x[c*PAD + j] - mu; var += dv*dv; }
        float rs = rsqrtf(var*(1.f/48.f) + 1e-5f);
        #pragma unroll
        for (int c = 0; c < 48; c++)
            s_x[c*PAD + j] = (s_x[c*PAD + j] - mu)*rs*s_g[c] + s_bb[c];
    }
    __syncthreads();

    // in_proj
    int c0 = e*24;
    for (int itx = tid; itx < 24*33; itx += 384) {
        int eg = itx/33, jg = itx%33;
        int e4 = eg*4, j4 = jg*4;
        float acc[4][4] = {};
        #pragma unroll
        for (int dd = 0; dd < 24; dd++) {
            float4 xv = *(const float4*)&s_x[(c0+dd)*PAD + j4];
            float4 wv = *(const float4*)&s_wi[dd*96 + e4];
            acc[0][0]+=wv.x*xv.x; acc[0][1]+=wv.x*xv.y; acc[0][2]+=wv.x*xv.z; acc[0][3]+=wv.x*xv.w;
            acc[1][0]+=wv.y*xv.x; acc[1][1]+=wv.y*xv.y; acc[1][2]+=wv.y*xv.z; acc[1][3]+=wv.y*xv.w;
            acc[2][0]+=wv.z*xv.x; acc[2][1]+=wv.z*xv.y; acc[2][2]+=wv.z*xv.z; acc[2][3]+=wv.z*xv.w;
            acc[3][0]+=wv.w*xv.x; acc[3][1]+=wv.w*xv.y; acc[3][2]+=wv.w*xv.z; acc[3][3]+=wv.w*xv.w;
        }
        int gl = l0 - 3 + j4;
        #pragma unroll
        for (int ee = 0; ee < 4; ee++) {
            int eo = e4 + ee;
            #pragma unroll
            for (int jj = 0; jj < 4; jj++) {
                int j = j4 + jj;
                if (j >= CHP) continue;
                float v = (gl + jj < 0) ? 0.f : acc[ee][jj];
                if (eo < 48) s_xz[eo*PAD + j] = v;
                else if (j >= 3) {
                    float zs = v / (1.f + __expf(-v));
                    gZs[((size_t)(be*48) + (eo-48))*LL + (size_t)(l0 + j - 3)] = zs;
                }
            }
        }
    }
    __syncthreads();

    // causal conv(4) + silu
    for (int itx = tid; itx < 48*CHN; itx += 384) {
        int d = itx/CHN, t = itx%CHN;
        float v = s_cb[d]
                + s_cw[d*4+0]*s_xz[d*PAD + t]
                + s_cw[d*4+1]*s_xz[d*PAD + t+1]
                + s_cw[d*4+2]*s_xz[d*PAD + t+2]
                + s_cw[d*4+3]*s_xz[d*PAD + t+3];
        s_xc[d*PAD + t] = v / (1.f + __expf(-v));
    }
    __syncthreads();

    // x_proj
    for (int itx = tid; itx < 18*32; itx += 384) {
        int e2 = itx/32, t4 = (itx%32)*4;
        float a[4] = {0,0,0,0};
        #pragma unroll
        for (int d = 0; d < 48; d++) {
            float w = s_xw[e2*48 + d];
            float4 xv = *(const float4*)&s_xc[d*PAD + t4];
            a[0] += w*xv.x; a[1] += w*xv.y; a[2] += w*xv.z; a[3] += w*xv.w;
        }
        if (e2 < 2) {
            float4 st = {a[0],a[1],a[2],a[3]};
            *(float4*)&s_dtin[e2*PAD + t4] = st;
        } else {
            int c = e2 - 2;
            int swz = ((t4 >> 4) & 7) * 4;
            #pragma unroll
            for (int k = 0; k < 4; k++)
                s_bt[(t4+k)*20 + swz + c] = a[k];
        }
    }
    __syncthreads();

    // gCm write (reads s_bt only)
    for (int itx = tid; itx < 8*CHN; itx += 384) {
        int ss = itx>>7, t = itx&127;
        gCm[(size_t)(be*8 + ss)*LL + l0 + t] = s_bt[t*20 + ((t>>4)&7)*4 + 8 + ss];
    }

    // ---- register-resident hierarchical scan: thread = (d, sub of 16 tokens) ----
    {
        int d = tid >> 3, sub = tid & 7;
        int t0 = sub * 16;
        const float* Aptr = A_log + p*384 + d*8;
        float A0 = -__expf(Aptr[0]);
        bool fast = true;
        #pragma unroll
        for (int s = 1; s < 8; s++) {
            float as = -__expf(Aptr[s]);
            if (fabsf(as - (float)(s+1)*A0) > 1e-4f*fabsf(as)) fast = false;
        }

        // dt = softplus(dt_in @ dtw^T + dtb) in registers
        float dtv[16];
        {
            float w0 = s_dtw[d*2], w1 = s_dtw[d*2+1], bs0 = s_dtb[d];
            #pragma unroll
            for (int k = 0; k < 4; k++) {
                float4 a0v = *(const float4*)&s_dtin[t0 + k*4];
                float4 a1v = *(const float4*)&s_dtin[PAD + t0 + k*4];
                float vv0 = bs0 + w0*a0v.x + w1*a1v.x;
                float vv1 = bs0 + w0*a0v.y + w1*a1v.y;
                float vv2 = bs0 + w0*a0v.z + w1*a1v.z;
                float vv3 = bs0 + w0*a0v.w + w1*a1v.w;
                dtv[k*4+0] = (vv0 > 20.f) ? vv0 : log1pf(__expf(vv0));
                dtv[k*4+1] = (vv1 > 20.f) ? vv1 : log1pf(__expf(vv1));
                dtv[k*4+2] = (vv2 > 20.f) ? vv2 : log1pf(__expf(vv2));
                dtv[k*4+3] = (vv3 > 20.f) ? vv3 : log1pf(__expf(vv3));
            }
        }

        float h[8] = {0,0,0,0,0,0,0,0};
        float y0l[16];
        float run = 0.f;
        if (fast) {
            #pragma unroll
            for (int k = 0; k < 4; k++) {
                float4 xcq = *(const float4*)&s_xc[d*PAD + t0 + k*4];
                float xcl[4] = {xcq.x, xcq.y, xcq.z, xcq.w};
                #pragma unroll
                for (int j = 0; j < 4; j++) {
                    int tt = k*4 + j, t = t0 + tt;
                    float dv = dtv[tt];
                    float dx = dv * xcl[j];
                    const float* rb = &s_bt[t*20 + sub*4];
                    float4 b0 = *(const float4*)rb;
                    float4 b1 = *(const float4*)(rb+4);
                    float4 cv0 = *(const float4*)(rb+8);
                    float4 cv1 = *(const float4*)(rb+12);
                    float q = __expf(dv * A0), pc = q;
                    float y0 = 0.f;
                    h[0] = pc*h[0] + dx*b0.x; y0 += h[0]*cv0.x; pc *= q;
                    h[1] = pc*h[1] + dx*b0.y; y0 += h[1]*cv0.y; pc *= q;
                    h[2] = pc*h[2] + dx*b0.z; y0 += h[2]*cv0.z; pc *= q;
                    h[3] = pc*h[3] + dx*b0.w; y0 += h[3]*cv0.w; pc *= q;
                    h[4] = pc*h[4] + dx*b1.x; y0 += h[4]*cv1.x; pc *= q;
                    h[5] = pc*h[5] + dx*b1.y; y0 += h[5]*cv1.y; pc *= q;
                    h[6] = pc*h[6] + dx*b1.z; y0 += h[6]*cv1.z; pc *= q;
                    h[7] = pc*h[7] + dx*b1.w; y0 += h[7]*cv1.w;
                    y0l[tt] = y0;
                    run += dv;
                    dtv[tt] = run;   // local inclusive prefix
                }
            }
        } else {
            #pragma unroll
            for (int k = 0; k < 4; k++) {
                float4 xcq = *(const float4*)&s_xc[d*PAD + t0 + k*4];
                float xcl[4] = {xcq.x, xcq.y, xcq.z, xcq.w};
                #pragma unroll
                for (int j = 0; j < 4; j++) {
                    int tt = k*4 + j, t = t0 + tt;
                    float dv = dtv[tt];
                    float dx = dv * xcl[j];
                    const float* rb = &s_bt[t*20 + sub*4];
                    float4 b0 = *(const float4*)rb;
                    float4 b1 = *(const float4*)(rb+4);
                    float4 cv0 = *(const float4*)(rb+8);
                    float4 cv1 = *(const float4*)(rb+12);
                    float Bv[8] = {b0.x,b0.y,b0.z,b0.w,b1.x,b1.y,b1.z,b1.w};
                    float Cv[8] = {cv0.x,cv0.y,cv0.z,cv0.w,cv1.x,cv1.y,cv1.z,cv1.w};
                    float y0 = 0.f;
                    #pragma unroll
                    for (int s = 0; s < 8; s++) {
                        float as = -__expf(Aptr[s]);
                        h[s] = __expf(dv*as)*h[s] + dx*Bv[s];
                        y0 += h[s]*Cv[s];
                    }
                    y0l[tt] = y0;
                    run += dv;
                    dtv[tt] = run;
                }
            }
        }

        // Kogge-Stone inclusive scan over 8 subs
        float S = run;
        #pragma unroll
        for (int st = 1; st < 8; st <<= 1) {
            float Sp = __shfl_up_sync(0xFFFFFFFFu, S, st, 8);
            float hp[8];
            #pragma unroll
            for (int s = 0; s < 8; s++) hp[s] = __shfl_up_sync(0xFFFFFFFFu, h[s], st, 8);
            if (sub >= st) {
                if (fast) {
                    float q = __expf(S * A0), pc = q;
                    #pragma unroll
                    for (int s = 0; s < 8; s++) { h[s] = pc*hp[s] + h[s]; pc *= q; }
                } else {
                    #pragma unroll
                    for (int s = 0; s < 8; s++) {
                        float as = -__expf(Aptr[s]);
                        h[s] = __expf(S*as)*hp[s] + h[s];
                    }
                }
                S += Sp;
            }
        }
        float Hex[8], Sex;
        #pragma unroll
        for (int s = 0; s < 8; s++) Hex[s] = __shfl_up_sync(0xFFFFFFFFu, h[s], 1, 8);
        Sex = __shfl_up_sync(0xFFFFFFFFu, S, 1, 8);
        if (sub == 0) {
            Sex = 0.f;
            #pragma unroll
            for (int s = 0; s < 8; s++) Hex[s] = 0.f;
        }
        if (sub == 7) {
            #pragma unroll
            for (int s = 0; s < 8; s++)
                gHend[(size_t)(be*NCHK + ck)*384 + d*8 + s] = h[s];
            gSsum[(size_t)(be*NCHK + ck)*48 + d] = S;
        }

        // pass 2: carry correction + direct float4 global stores
        float Dpd = s_Dp[d];
        size_t gb = (size_t)(be*48 + d)*LL + l0 + t0;
        #pragma unroll
        for (int k = 0; k < 4; k++) {
            float4 xcq = *(const float4*)&s_xc[d*PAD + t0 + k*4];
            float xcl[4] = {xcq.x, xcq.y, xcq.z, xcq.w};
            float yo[4], so[4];
            #pragma unroll
            for (int j = 0; j < 4; j++) {
                int tt = k*4 + j, t = t0 + tt;
                float Sloc = dtv[tt];
                float y = y0l[tt];
                const float* rb = &s_bt[t*20 + sub*4 + 8];
                float4 cv0 = *(const float4*)rb;
                float4 cv1 = *(const float4*)(rb+4);
                if (fast) {
                    float r = __expf(Sloc * A0), pc = r;
                    y += cv0.x*pc*Hex[0]; pc *= r;
                    y += cv0.y*pc*Hex[1]; pc *= r;
                    y += cv0.z*pc*Hex[2]; pc *= r;
                    y += cv0.w*pc*Hex[3]; pc *= r;
                    y += cv1.x*pc*Hex[4]; pc *= r;
                    y += cv1.y*pc*Hex[5]; pc *= r;
                    y += cv1.z*pc*Hex[6]; pc *= r;
                    y += cv1.w*pc*Hex[7];
                } else {
                    float Cv[8] = {cv0.x,cv0.y,cv0.z,cv0.w,cv1.x,cv1.y,cv1.z,cv1.w};
                    #pragma unroll
                    for (int s = 0; s < 8; s++) {
                        float as = -__expf(Aptr[s]);
                        y += Cv[s]*__expf(Sloc*as)*Hex[s];
                    }
                }
                yo[j] = y + xcl[j]*Dpd;
                so[j] = Sloc + Sex;
            }
            float4 yq = {yo[0],yo[1],yo[2],yo[3]};
            float4 sq = {so[0],so[1],so[2],so[3]};
            *(float4*)&gY0 [gb + k*4] = yq;
            *(float4*)&gSdt[gb + k*4] = sq;
        }
    }
}

// ---------------- K2: serial carry combine ----------------
__global__ __launch_bounds__(384) void k_combine(const float* __restrict__ A_log, int iter)
{
    int be = blockIdx.x, e = be & 1, p = 2*iter + e;
    int tid = threadIdx.x, d = tid >> 3;
    float A_ds = -expf(A_log[p*384 + tid]);
    float hrun = 0.f;
    const int G = 16;
    float hv[G], Sv[G];
    for (int g0 = 0; g0 < NCHK; g0 += G) {
        #pragma unroll
        for (int k = 0; k < G; k++) {
            int ck = g0 + k;
            hv[k] = gHend[(size_t)(be*NCHK + ck)*384 + tid];
            Sv[k] = gSsum[(size_t)(be*NCHK + ck)*48 + d];
        }
        #pragma unroll
        for (int k = 0; k < G; k++) {
            int ck = g0 + k;
            gH0c[(size_t)(be*NCHK + ck)*384 + tid] = hrun;
            hrun = __expf(Sv[k]*A_ds)*hrun + hv[k];
        }
    }
}

// ---------------- K3: correction + gate + out_proj + residual (float4) ----------------
__global__ __launch_bounds__(384, 2) void k_output(
    const float* __restrict__ A_log, const float* __restrict__ out_w,
    const float* __restrict__ xext, int useX, int iter)
{
    int ck = blockIdx.x, e = blockIdx.y, b = blockIdx.z;
    int p = 2*iter + e, be = b*2 + e, l0 = ck*CHN, tid = threadIdx.x;

    extern __shared__ float sm[];
    float* s_y    = sm;              // [48][128]
    float* s_Cm   = s_y  + 48*128;   // [8][128]
    float* s_h0   = s_Cm + 8*128;    // [384]
    float* s_A    = s_h0 + 384;      // [384]
    float* s_ow   = s_A  + 384;      // [24][48]
    float* s_fast = s_ow + 24*48;    // [48]

    s_h0[tid] = gH0c[(size_t)(be*NCHK + ck)*384 + tid];
    s_A[tid]  = -__expf(A_log[p*384 + tid]);
    for (int i = tid; i < 24*48; i += 384) s_ow[i] = out_w[p*1152 + i];
    for (int i = tid; i < 8*32; i += 384) {
        int ss = i>>5, tq = (i&31)*4;
        *(float4*)&s_Cm[ss*128 + tq] = *(const float4*)&gCm[(size_t)(be*8 + ss)*LL + l0 + tq];
    }
    if (tid < 48) {
        float a0 = -__expf(A_log[p*384 + tid*8]);
        float ok = 1.f;
        #pragma unroll
        for (int s = 1; s < 8; s++) {
            float as = -__expf(A_log[p*384 + tid*8 + s]);
            if (fabsf(as - (float)(s+1)*a0) > 1e-4f * fabsf(as)) ok = 0.f;
        }
        s_fast[tid] = ok;
    }
    __syncthreads();

    size_t baseF = (size_t)(be*48)*LL + l0;
    for (int itx = tid; itx < 48*32; itx += 384) {
        int d = itx>>5, tq = (itx&31)*4;
        size_t g = baseF + (size_t)d*LL + tq;
        float4 sd4 = *(const float4*)&gSdt[g];
        float4 y4  = *(const float4*)&gY0 [g];
        float4 z4  = *(const float4*)&gZs [g];
        float acc[4] = {y4.x, y4.y, y4.z, y4.w};
        if (s_fast[d] != 0.f) {
            float A0d = s_A[d*8];
            float r0 = __expf(sd4.x*A0d), r1 = __expf(sd4.y*A0d);
            float r2 = __expf(sd4.z*A0d), r3 = __expf(sd4.w*A0d);
            float p0 = r0, p1 = r1, p2 = r2, p3 = r3;
            #pragma unroll
            for (int s = 0; s < 8; s++) {
                float4 cm = *(const float4*)&s_Cm[s*128 + tq];
                float hh = s_h0[d*8 + s];
                acc[0] += cm.x*p0*hh; acc[1] += cm.y*p1*hh;
                acc[2] += cm.z*p2*hh; acc[3] += cm.w*p3*hh;
                p0 *= r0; p1 *= r1; p2 *= r2; p3 *= r3;
            }
        } else {
            float sdv[4] = {sd4.x, sd4.y, sd4.z, sd4.w};
            #pragma unroll
            for (int s = 0; s < 8; s++) {
                float4 cm = *(const float4*)&s_Cm[s*128 + tq];
                float hh = s_h0[d*8 + s];
                float As = s_A[d*8 + s];
                acc[0] += cm.x*__expf(sdv[0]*As)*hh;
                acc[1] += cm.y*__expf(sdv[1]*As)*hh;
                acc[2] += cm.z*__expf(sdv[2]*As)*hh;
                acc[3] += cm.w*__expf(sdv[3]*As)*hh;
            }
        }
        float4 yq = {acc[0]*z4.x, acc[1]*z4.y, acc[2]*z4.z, acc[3]*z4.w};
        *(float4*)&s_y[d*128 + tq] = yq;
    }
    __syncthreads();

    const float* resb = (useX ? xext : (const float*)gXf);
    for (int itx = tid; itx < 24*32; itx += 384) {
        int m = itx>>5, tq = (itx&31)*4;
        float a0=0.f, a1=0.f, a2=0.f, a3=0.f;
        #pragma unroll
        for (int d = 0; d < 48; d++) {
            float w = s_ow[m*48 + d];
            float4 yv = *(const float4*)&s_y[d*128 + tq];
            a0 += w*yv.x; a1 += w*yv.y; a2 += w*yv.z; a3 += w*yv.w;
        }
        int c = e*24 + m;
        size_t rowb = (size_t)(b*48 + c)*LL;
        if (e == 0) {
            size_t o = rowb + l0 + tq;
            float4 r = *(const float4*)&resb[o];
            float4 st = {a0+r.x, a1+r.y, a2+r.z, a3+r.w};
            *(float4*)&gYf[o] = st;
        } else {
            size_t o = rowb + (size_t)(LL - 4 - l0 - tq);
            float4 r = *(const float4*)&resb[o];
            float4 st = {a3+r.x, a2+r.y, a1+r.z, a0+r.w};
            *(float4*)&gYf[o] = st;
        }
    }
}

#define SMEM_K1 ((3*48*PAD + 2*PAD + 2592 + 24*96 + 192 + 48 + 864 + 96 + 48 + 48 + 48 + 48) * 4)
#define SMEM_K3 ((48*128 + 8*128 + 384 + 384 + 24*48 + 48) * 4)

extern "C" void kernel_launch(void* const* d_in, const int* in_sizes, int n_in,
                              void* d_out, int out_size)
{
    const float* x       = (const float*)d_in[0];
    const float* ln_g    = (const float*)d_in[1];
    const float* ln_b    = (const float*)d_in[2];
    const float* in_w    = (const float*)d_in[3];
    const float* conv_w  = (const float*)d_in[4];
    const float* conv_b  = (const float*)d_in[5];
    const float* xproj_w = (const float*)d_in[6];
    const float* dt_w    = (const float*)d_in[7];
    const float* dt_b    = (const float*)d_in[8];
    const float* A_log   = (const float*)d_in[9];
    const float* Dp      = (const float*)d_in[10];
    const float* out_w   = (const float*)d_in[11];
    float* out = (float*)d_out;

    cudaFuncSetAttribute(k_features, cudaFuncAttributeMaxDynamicSharedMemorySize, SMEM_K1);

    dim3 pg(32, 96), pb(32, 32);
    for (int it = 0; it < 3; ++it) {
        int useX = (it == 0) ? 1 : 0;
        k_features<<<dim3(NCHK,2,2), 384, SMEM_K1>>>(ln_g, ln_b, in_w, conv_w, conv_b,
                                                     xproj_w, dt_w, dt_b, A_log, Dp,
                                                     x, useX, it);
        k_combine<<<4, 384>>>(A_log, it);
        k_output<<<dim3(NCHK,2,2), 384, SMEM_K3>>>(A_log, out_w, x, useX, it);
        if (it < 2) k_rot<<<pg, pb>>>();
        else        k_final<<<pg, pb>>>(out, x);
    }
}